// round 1
// baseline (speedup 1.0000x reference)
#include <cuda_runtime.h>
#include <cuda_bf16.h>
#include <math.h>

// Problem constants (fixed by the dataset)
#define N_NODES 140000
#define N_EDGES 2240000
#define NFEAT   128
#define NHID    128
#define N_FRAMES 14

// Scratch in device globals (allocation-free rule)
__device__ float g_support[(size_t)N_NODES * NHID];   // x @ W
__device__ float g_h[(size_t)N_NODES * NHID];         // relu(agg + b)
__device__ int   g_rowptr[N_NODES + 1];

// ---------------------------------------------------------------------------
// Kernel 1: support = x @ W   (M=140000, K=128, N=128) fp32
// Block: 128 rows x 128 cols, 256 threads, 8x8 register tile per thread.
// K staged in chunks of 32 through shared memory (stays under 48KB static).
// ---------------------------------------------------------------------------
__global__ __launch_bounds__(256)
void gemm_kernel(const float* __restrict__ x, const float* __restrict__ W,
                 int nrows)
{
    __shared__ float Xs[128][36];   // [row][k_local], padded to 36 (16B-aligned rows)
    __shared__ float Ws[32][128];   // [k_local][col]

    const int tid = threadIdx.x;
    const int m0  = blockIdx.x * 128;

    const int ty = tid >> 4;        // 0..15  -> row group
    const int tx = tid & 15;        // 0..15  -> col group
    const int r0 = ty * 8;
    const int c0 = tx * 8;

    float acc[8][8];
#pragma unroll
    for (int i = 0; i < 8; ++i)
#pragma unroll
        for (int j = 0; j < 8; ++j) acc[i][j] = 0.f;

    for (int ks = 0; ks < 128; ks += 32) {
        // ---- load stage: Xs[128][32], Ws[32][128] ----
        // Xs: 1024 float4, 4 per thread
#pragma unroll
        for (int t = 0; t < 4; ++t) {
            int i = tid + t * 256;          // 0..1023
            int r = i >> 3;                 // 0..127
            int c = (i & 7) << 2;           // 0,4,...,28
            int gr = m0 + r;
            float4 v = make_float4(0.f, 0.f, 0.f, 0.f);
            if (gr < nrows)
                v = *(const float4*)&x[(size_t)gr * NFEAT + ks + c];
            *(float4*)&Xs[r][c] = v;
        }
        // Ws: 1024 float4, 4 per thread
#pragma unroll
        for (int t = 0; t < 4; ++t) {
            int i = tid + t * 256;          // 0..1023
            int r = i >> 5;                 // 0..31
            int c = (i & 31) << 2;          // 0..124
            *(float4*)&Ws[r][c] = *(const float4*)&W[(size_t)(ks + r) * NHID + c];
        }
        __syncthreads();

        // ---- compute 32 k's ----
#pragma unroll
        for (int k = 0; k < 32; k += 4) {
            float4 a4[8];
#pragma unroll
            for (int i = 0; i < 8; ++i)
                a4[i] = *(const float4*)&Xs[r0 + i][k];

#pragma unroll
            for (int kk = 0; kk < 4; ++kk) {
                float4 bva = *(const float4*)&Ws[k + kk][c0];
                float4 bvb = *(const float4*)&Ws[k + kk][c0 + 4];
                float bb[8] = {bva.x, bva.y, bva.z, bva.w,
                               bvb.x, bvb.y, bvb.z, bvb.w};
#pragma unroll
                for (int i = 0; i < 8; ++i) {
                    float av = (kk == 0) ? a4[i].x :
                               (kk == 1) ? a4[i].y :
                               (kk == 2) ? a4[i].z : a4[i].w;
#pragma unroll
                    for (int j = 0; j < 8; ++j)
                        acc[i][j] = fmaf(av, bb[j], acc[i][j]);
                }
            }
        }
        __syncthreads();
    }

    // ---- store ----
#pragma unroll
    for (int i = 0; i < 8; ++i) {
        int gr = m0 + r0 + i;
        if (gr < nrows) {
            float4 v0 = make_float4(acc[i][0], acc[i][1], acc[i][2], acc[i][3]);
            float4 v1 = make_float4(acc[i][4], acc[i][5], acc[i][6], acc[i][7]);
            *(float4*)&g_support[(size_t)gr * NHID + c0]     = v0;
            *(float4*)&g_support[(size_t)gr * NHID + c0 + 4] = v1;
        }
    }
}

// ---------------------------------------------------------------------------
// Kernel 2: CSR row_ptr from sorted edge_row via binary search (lower_bound)
// ---------------------------------------------------------------------------
__global__ void rowptr_kernel(const int* __restrict__ erow, int nnodes, int nedges)
{
    int n = blockIdx.x * blockDim.x + threadIdx.x;
    if (n > nnodes) return;
    int lo = 0, hi = nedges;
    while (lo < hi) {
        int mid = (lo + hi) >> 1;
        if (erow[mid] < n) lo = mid + 1;
        else hi = mid;
    }
    g_rowptr[n] = lo;
}

// ---------------------------------------------------------------------------
// Kernel 3: h[n] = relu( sum_e val[e]*support[col[e]] + b ), one block per node
// 128 threads = one feature each; edge col/val staged through SMEM.
// ---------------------------------------------------------------------------
__global__ __launch_bounds__(128)
void spmm_kernel(const float* __restrict__ b,
                 const float* __restrict__ eval,
                 const int*   __restrict__ ecol)
{
    const int n   = blockIdx.x;
    const int tid = threadIdx.x;

    const int s = g_rowptr[n];
    const int e = g_rowptr[n + 1];

    __shared__ int   scol[128];
    __shared__ float sval[128];

    float acc = 0.f;
    for (int base = s; base < e; base += 128) {
        int cnt = min(128, e - base);
        if (tid < cnt) {
            scol[tid] = ecol[base + tid];
            sval[tid] = eval[base + tid];
        }
        __syncthreads();
        int j = 0;
        // 2-way unrolled for load-level parallelism
        for (; j + 1 < cnt; j += 2) {
            float v0 = sval[j],     v1 = sval[j + 1];
            const float* p0 = &g_support[(size_t)scol[j]     * NHID + tid];
            const float* p1 = &g_support[(size_t)scol[j + 1] * NHID + tid];
            float x0 = __ldg(p0);
            float x1 = __ldg(p1);
            acc = fmaf(v0, x0, acc);
            acc = fmaf(v1, x1, acc);
        }
        if (j < cnt)
            acc = fmaf(sval[j], __ldg(&g_support[(size_t)scol[j] * NHID + tid]), acc);
        __syncthreads();
    }

    float v = acc + b[tid];
    g_h[(size_t)n * NHID + tid] = fmaxf(v, 0.f);
}

// ---------------------------------------------------------------------------
// Kernel 4: max over 14 frames + log_softmax over 128 features.
// One block (128 threads) per output row g.
// ---------------------------------------------------------------------------
__global__ __launch_bounds__(128)
void head_kernel(float* __restrict__ out, int ng)
{
    const int g   = blockIdx.x;
    const int tid = threadIdx.x;

    float v = -INFINITY;
#pragma unroll
    for (int f = 0; f < N_FRAMES; ++f)
        v = fmaxf(v, g_h[(size_t)(f * ng + g) * NHID + tid]);

    __shared__ float sred[4];
    const int w = tid >> 5, l = tid & 31;

    // block max
    float m = v;
#pragma unroll
    for (int o = 16; o; o >>= 1) m = fmaxf(m, __shfl_xor_sync(0xffffffffu, m, o));
    if (l == 0) sred[w] = m;
    __syncthreads();
    m = fmaxf(fmaxf(sred[0], sred[1]), fmaxf(sred[2], sred[3]));
    __syncthreads();

    // block sum of exp
    float ex = expf(v - m);
    float s = ex;
#pragma unroll
    for (int o = 16; o; o >>= 1) s += __shfl_xor_sync(0xffffffffu, s, o);
    if (l == 0) sred[w] = s;
    __syncthreads();
    s = sred[0] + sred[1] + sred[2] + sred[3];

    out[(size_t)g * NHID + tid] = v - m - logf(s);
}

// ---------------------------------------------------------------------------
extern "C" void kernel_launch(void* const* d_in, const int* in_sizes, int n_in,
                              void* d_out, int out_size)
{
    const float* x    = (const float*)d_in[0];
    const float* W    = (const float*)d_in[1];
    const float* b    = (const float*)d_in[2];
    const float* evl  = (const float*)d_in[3];
    const int*   erow = (const int*)  d_in[4];
    const int*   ecol = (const int*)  d_in[5];
    float* out = (float*)d_out;

    const int N  = in_sizes[0] / NFEAT;   // 140000
    const int E  = in_sizes[3];           // 2240000
    const int NG = N / N_FRAMES;          // 10000

    gemm_kernel<<<(N + 127) / 128, 256>>>(x, W, N);
    rowptr_kernel<<<(N + 1 + 255) / 256, 256>>>(erow, N, E);
    spmm_kernel<<<N, 128>>>(b, evl, ecol);
    head_kernel<<<NG, 128>>>(out, NG);
}

// round 4
// speedup vs baseline: 1.5233x; 1.5233x over previous
#include <cuda_runtime.h>
#include <cuda_bf16.h>
#include <math.h>

#define N_NODES 140000
#define N_EDGES 2240000
#define NFEAT   128
#define NHID    128
#define N_FRAMES 14

// Scratch (allocation-free rule: device globals)
__device__ float g_support[(size_t)N_NODES * NHID];   // x @ W
__device__ float g_h[(size_t)N_NODES * NHID];         // relu(agg + b)
__device__ int   g_rowptr[N_NODES + 1];

// ---------------------------------------------------------------------------
// tf32 helpers
// ---------------------------------------------------------------------------
__device__ __forceinline__ void split_tf32(float f, unsigned& hi, unsigned& lo)
{
    asm("cvt.rna.tf32.f32 %0, %1;" : "=r"(hi) : "f"(f));
    float r = f - __uint_as_float(hi);
    asm("cvt.rna.tf32.f32 %0, %1;" : "=r"(lo) : "f"(r));
}

__device__ __forceinline__ void mma_tf32(float* c, const unsigned* a,
                                         unsigned b0, unsigned b1)
{
    asm volatile(
        "mma.sync.aligned.m16n8k8.row.col.f32.tf32.tf32.f32 "
        "{%0,%1,%2,%3}, {%4,%5,%6,%7}, {%8,%9}, {%0,%1,%2,%3};\n"
        : "+f"(c[0]), "+f"(c[1]), "+f"(c[2]), "+f"(c[3])
        : "r"(a[0]), "r"(a[1]), "r"(a[2]), "r"(a[3]), "r"(b0), "r"(b1));
}

// ---------------------------------------------------------------------------
// Kernel 1: support = x @ W  via tensor cores, 3-term tf32 split (~fp32 acc).
// Block = 128 threads (4 warps). Block tile: 128 rows x 128 cols.
// Each warp: 32 rows (two m16 fragment row-sets) x all 128 cols -> B reuse x2.
// K chunked by 16 through SMEM. W staged TRANSPOSED + pre-split as uint2{hi,lo}.
// ---------------------------------------------------------------------------
__global__ __launch_bounds__(128)
void gemm_tc_kernel(const float* __restrict__ x, const float* __restrict__ W,
                    int nrows)
{
    __shared__ float Xs[128][20];       // [row][k_local], pad 20 (conflict-free frag loads)
    __shared__ uint2 Wst[128][20];      // [n_col][k_local] -> {tf32_hi, tf32_lo}

    const int tid  = threadIdx.x;
    const int lane = tid & 31;
    const int w    = tid >> 5;          // warp 0..3
    const int g    = lane >> 2;         // groupID 0..7
    const int tg   = lane & 3;          // thread-in-group 0..3
    const int m0   = blockIdx.x * 128;

    float acc0[16][4];                  // rows w*32 + {g, g+8}
    float acc1[16][4];                  // rows w*32 + {g+16, g+24}
#pragma unroll
    for (int nt = 0; nt < 16; ++nt)
#pragma unroll
        for (int i = 0; i < 4; ++i) { acc0[nt][i] = 0.f; acc1[nt][i] = 0.f; }

    for (int ks = 0; ks < 128; ks += 16) {
        // ---- stage Xs: 128 rows x 16 k  (512 float4 / 128 threads = 4 each) ----
#pragma unroll
        for (int t = 0; t < 4; ++t) {
            int i  = tid + t * 128;     // 0..511
            int r  = i >> 2;            // 0..127
            int c  = (i & 3) << 2;      // 0,4,8,12
            int gr = m0 + r;
            float4 v = make_float4(0.f, 0.f, 0.f, 0.f);
            if (gr < nrows)
                v = *(const float4*)&x[(size_t)gr * NFEAT + ks + c];
            *(float4*)&Xs[r][c] = v;
        }
        // ---- stage Wst: read W[ks+r][c], write transposed+split ----
#pragma unroll
        for (int t = 0; t < 4; ++t) {
            int i  = tid + t * 128;     // 0..511
            int r  = i >> 5;            // 0..15 (k_local)
            int c4 = (i & 31) << 2;     // 0..124
            float4 wv = *(const float4*)&W[(size_t)(ks + r) * NHID + c4];
            unsigned hi, lo;
            split_tf32(wv.x, hi, lo); Wst[c4 + 0][r] = make_uint2(hi, lo);
            split_tf32(wv.y, hi, lo); Wst[c4 + 1][r] = make_uint2(hi, lo);
            split_tf32(wv.z, hi, lo); Wst[c4 + 2][r] = make_uint2(hi, lo);
            split_tf32(wv.w, hi, lo); Wst[c4 + 3][r] = make_uint2(hi, lo);
        }
        __syncthreads();

#pragma unroll
        for (int k = 0; k < 16; k += 8) {
            const int r0 = w * 32 + g;
            unsigned ahi0[4], alo0[4], ahi1[4], alo1[4];
            split_tf32(Xs[r0     ][k + tg    ], ahi0[0], alo0[0]);
            split_tf32(Xs[r0 +  8][k + tg    ], ahi0[1], alo0[1]);
            split_tf32(Xs[r0     ][k + tg + 4], ahi0[2], alo0[2]);
            split_tf32(Xs[r0 +  8][k + tg + 4], ahi0[3], alo0[3]);
            split_tf32(Xs[r0 + 16][k + tg    ], ahi1[0], alo1[0]);
            split_tf32(Xs[r0 + 24][k + tg    ], ahi1[1], alo1[1]);
            split_tf32(Xs[r0 + 16][k + tg + 4], ahi1[2], alo1[2]);
            split_tf32(Xs[r0 + 24][k + tg + 4], ahi1[3], alo1[3]);

#pragma unroll
            for (int nt = 0; nt < 16; ++nt) {
                uint2 p0 = Wst[nt * 8 + g][k + tg];       // b0 {hi,lo}
                uint2 p1 = Wst[nt * 8 + g][k + tg + 4];   // b1 {hi,lo}
                mma_tf32(acc0[nt], ahi0, p0.x, p1.x);
                mma_tf32(acc0[nt], ahi0, p0.y, p1.y);
                mma_tf32(acc0[nt], alo0, p0.x, p1.x);
                mma_tf32(acc1[nt], ahi1, p0.x, p1.x);
                mma_tf32(acc1[nt], ahi1, p0.y, p1.y);
                mma_tf32(acc1[nt], alo1, p0.x, p1.x);
            }
        }
        __syncthreads();
    }

    // ---- store ----
    const int ra = m0 + w * 32 + g;
    const bool ok0 = (ra      < nrows);
    const bool ok1 = (ra +  8 < nrows);
    const bool ok2 = (ra + 16 < nrows);
    const bool ok3 = (ra + 24 < nrows);
#pragma unroll
    for (int nt = 0; nt < 16; ++nt) {
        int col = nt * 8 + tg * 2;
        if (ok0) *(float2*)&g_support[(size_t)(ra     ) * NHID + col] = make_float2(acc0[nt][0], acc0[nt][1]);
        if (ok1) *(float2*)&g_support[(size_t)(ra +  8) * NHID + col] = make_float2(acc0[nt][2], acc0[nt][3]);
        if (ok2) *(float2*)&g_support[(size_t)(ra + 16) * NHID + col] = make_float2(acc1[nt][0], acc1[nt][1]);
        if (ok3) *(float2*)&g_support[(size_t)(ra + 24) * NHID + col] = make_float2(acc1[nt][2], acc1[nt][3]);
    }
}

// ---------------------------------------------------------------------------
// Kernel 2: CSR row_ptr via binary search on sorted edge_row
// ---------------------------------------------------------------------------
__global__ void rowptr_kernel(const int* __restrict__ erow, int nnodes, int nedges)
{
    int n = blockIdx.x * blockDim.x + threadIdx.x;
    if (n > nnodes) return;
    int lo = 0, hi = nedges;
    while (lo < hi) {
        int mid = (lo + hi) >> 1;
        if (erow[mid] < n) lo = mid + 1;
        else hi = mid;
    }
    g_rowptr[n] = lo;
}

// ---------------------------------------------------------------------------
// Kernel 3: SpMM — one WARP per node, one float4 (4 feats) per lane.
// Streaming hints keep `support` resident in L2.
// ---------------------------------------------------------------------------
__device__ __forceinline__ float4 ld_row(const float* p)
{
    return *(const float4*)p;
}

__global__ __launch_bounds__(256)
void spmm_kernel(const float* __restrict__ bias,
                 const float* __restrict__ eval,
                 const int*   __restrict__ ecol)
{
    const int node = blockIdx.x * 8 + (threadIdx.x >> 5);
    const int lane = threadIdx.x & 31;
    if (node >= N_NODES) return;

    const int s = g_rowptr[node];
    const int e = g_rowptr[node + 1];
    const int fo = lane * 4;

    float4 acc = make_float4(0.f, 0.f, 0.f, 0.f);

    int j = s;
    for (; j + 4 <= e; j += 4) {
        int   c0 = __ldcs(&ecol[j]),     c1 = __ldcs(&ecol[j + 1]);
        int   c2 = __ldcs(&ecol[j + 2]), c3 = __ldcs(&ecol[j + 3]);
        float v0 = __ldcs(&eval[j]),     v1 = __ldcs(&eval[j + 1]);
        float v2 = __ldcs(&eval[j + 2]), v3 = __ldcs(&eval[j + 3]);
        float4 x0 = ld_row(&g_support[(size_t)c0 * NHID + fo]);
        float4 x1 = ld_row(&g_support[(size_t)c1 * NHID + fo]);
        float4 x2 = ld_row(&g_support[(size_t)c2 * NHID + fo]);
        float4 x3 = ld_row(&g_support[(size_t)c3 * NHID + fo]);
        acc.x = fmaf(v0, x0.x, acc.x); acc.y = fmaf(v0, x0.y, acc.y);
        acc.z = fmaf(v0, x0.z, acc.z); acc.w = fmaf(v0, x0.w, acc.w);
        acc.x = fmaf(v1, x1.x, acc.x); acc.y = fmaf(v1, x1.y, acc.y);
        acc.z = fmaf(v1, x1.z, acc.z); acc.w = fmaf(v1, x1.w, acc.w);
        acc.x = fmaf(v2, x2.x, acc.x); acc.y = fmaf(v2, x2.y, acc.y);
        acc.z = fmaf(v2, x2.z, acc.z); acc.w = fmaf(v2, x2.w, acc.w);
        acc.x = fmaf(v3, x3.x, acc.x); acc.y = fmaf(v3, x3.y, acc.y);
        acc.z = fmaf(v3, x3.z, acc.z); acc.w = fmaf(v3, x3.w, acc.w);
    }
    for (; j < e; ++j) {
        int   c = __ldcs(&ecol[j]);
        float v = __ldcs(&eval[j]);
        float4 xv = ld_row(&g_support[(size_t)c * NHID + fo]);
        acc.x = fmaf(v, xv.x, acc.x); acc.y = fmaf(v, xv.y, acc.y);
        acc.z = fmaf(v, xv.z, acc.z); acc.w = fmaf(v, xv.w, acc.w);
    }

    float4 bb = *(const float4*)&bias[fo];
    float4 r;
    r.x = fmaxf(acc.x + bb.x, 0.f);
    r.y = fmaxf(acc.y + bb.y, 0.f);
    r.z = fmaxf(acc.z + bb.z, 0.f);
    r.w = fmaxf(acc.w + bb.w, 0.f);
    // streaming store: don't evict `support` from L2
    __stcs((float4*)&g_h[(size_t)node * NHID + fo], r);
}

// ---------------------------------------------------------------------------
// Kernel 4: frame-max + log_softmax. One WARP per output row, float4/lane.
// ---------------------------------------------------------------------------
__global__ __launch_bounds__(256)
void head_kernel(float* __restrict__ out, int ng)
{
    const int row  = blockIdx.x * 8 + (threadIdx.x >> 5);
    const int lane = threadIdx.x & 31;
    if (row >= ng) return;
    const int fo = lane * 4;

    float4 v = make_float4(-INFINITY, -INFINITY, -INFINITY, -INFINITY);
#pragma unroll
    for (int f = 0; f < N_FRAMES; ++f) {
        float4 t = *(const float4*)&g_h[(size_t)(f * ng + row) * NHID + fo];
        v.x = fmaxf(v.x, t.x); v.y = fmaxf(v.y, t.y);
        v.z = fmaxf(v.z, t.z); v.w = fmaxf(v.w, t.w);
    }

    // warp max
    float m = fmaxf(fmaxf(v.x, v.y), fmaxf(v.z, v.w));
#pragma unroll
    for (int o = 16; o; o >>= 1) m = fmaxf(m, __shfl_xor_sync(0xffffffffu, m, o));

    // warp sum of exp
    float s = expf(v.x - m) + expf(v.y - m) + expf(v.z - m) + expf(v.w - m);
#pragma unroll
    for (int o = 16; o; o >>= 1) s += __shfl_xor_sync(0xffffffffu, s, o);

    float ls = m + logf(s);
    float4 r = make_float4(v.x - ls, v.y - ls, v.z - ls, v.w - ls);
    *(float4*)&out[(size_t)row * NHID + fo] = r;
}

// ---------------------------------------------------------------------------
extern "C" void kernel_launch(void* const* d_in, const int* in_sizes, int n_in,
                              void* d_out, int out_size)
{
    const float* x    = (const float*)d_in[0];
    const float* W    = (const float*)d_in[1];
    const float* b    = (const float*)d_in[2];
    const float* evl  = (const float*)d_in[3];
    const int*   erow = (const int*)  d_in[4];
    const int*   ecol = (const int*)  d_in[5];
    float* out = (float*)d_out;

    const int N  = in_sizes[0] / NFEAT;   // 140000
    const int E  = in_sizes[3];           // 2240000
    const int NG = N / N_FRAMES;          // 10000

    rowptr_kernel<<<(N + 1 + 255) / 256, 256>>>(erow, N, E);
    gemm_tc_kernel<<<(N + 127) / 128, 128>>>(x, W, N);
    spmm_kernel<<<(N + 7) / 8, 256>>>(b, evl, ecol);
    head_kernel<<<(NG + 7) / 8, 256>>>(out, NG);
}

// round 7
// speedup vs baseline: 2.0030x; 1.3150x over previous
#include <cuda_runtime.h>
#include <cuda_fp16.h>
#include <cuda_bf16.h>
#include <math.h>
#include <stdint.h>

#define N_NODES 140000
#define N_EDGES 2240000
#define NFEAT   128
#define NHID    128
#define N_FRAMES 14

// Scratch (allocation-free rule: device globals)
__device__ __half         g_supp[(size_t)N_NODES * NHID];  // x@W in fp16 (35.8 MB, L2-resident)
__device__ __nv_bfloat16  g_wprep[NHID * 256];             // [n][0:128 w_hi | 128:256 w_mid], K-major
__device__ int            g_rowptr[N_NODES + 1];

// ---------------------------------------------------------------------------
// bf16 m16n8k16 mma (fp32 accum)
// ---------------------------------------------------------------------------
__device__ __forceinline__ void mma_bf16(float* c, const uint32_t* a,
                                         uint32_t b0, uint32_t b1)
{
    asm volatile(
        "mma.sync.aligned.m16n8k16.row.col.f32.bf16.bf16.f32 "
        "{%0,%1,%2,%3}, {%4,%5,%6,%7}, {%8,%9}, {%0,%1,%2,%3};\n"
        : "+f"(c[0]), "+f"(c[1]), "+f"(c[2]), "+f"(c[3])
        : "r"(a[0]), "r"(a[1]), "r"(a[2]), "r"(a[3]), "r"(b0), "r"(b1));
}

// ---------------------------------------------------------------------------
// Kernel 0: split W (fp32 [K][N]) -> g_wprep bf16 [n][hi(128)|mid(128)] K-major
// ---------------------------------------------------------------------------
__global__ void prep_w(const float* __restrict__ W)
{
    const int k = blockIdx.x;     // 0..127
    const int n = threadIdx.x;    // 0..127
    float v = W[k * NHID + n];
    __nv_bfloat16 hi  = __float2bfloat16(v);
    __nv_bfloat16 mid = __float2bfloat16(v - __bfloat162float(hi));
    g_wprep[n * 256 + k]       = hi;
    g_wprep[n * 256 + 128 + k] = mid;
}

// ---------------------------------------------------------------------------
// Kernel 1: CSR row_ptr via binary search on sorted edge_row
// ---------------------------------------------------------------------------
__global__ void rowptr_kernel(const int* __restrict__ erow, int nnodes, int nedges)
{
    int n = blockIdx.x * blockDim.x + threadIdx.x;
    if (n > nnodes) return;
    int lo = 0, hi = nedges;
    while (lo < hi) {
        int mid = (lo + hi) >> 1;
        if (erow[mid] < n) lo = mid + 1;
        else hi = mid;
    }
    g_rowptr[n] = lo;
}

// ---------------------------------------------------------------------------
// Kernel 2: support = x @ W via bf16 m16n8k16 mma, 3-term split, fp32 accum.
// 256 threads (8 warps). Block tile 128x128; warp = 32 rows x 64 cols.
// K chunked by 32 fp32 (= 2 k16 bf16 steps, hi|mid in cols [0:32)|[32:64)).
// ---------------------------------------------------------------------------
__global__ __launch_bounds__(256)
void gemm_bf16(const float* __restrict__ x, int nrows)
{
    __shared__ union {
        struct { __nv_bfloat16 X[128][72]; __nv_bfloat16 W[128][72]; } s;
        __half O[128][136];
    } sh;

    const int tid  = threadIdx.x;
    const int lane = tid & 31;
    const int w    = tid >> 5;
    const int g    = lane >> 2;     // 0..7
    const int tg   = lane & 3;      // 0..3
    const int rbase = (w & 3) * 32;
    const int cbase = (w >> 2) * 64;
    const int m0   = blockIdx.x * 128;

    float acc0[8][4], acc1[8][4];
#pragma unroll
    for (int nt = 0; nt < 8; ++nt)
#pragma unroll
        for (int i = 0; i < 4; ++i) { acc0[nt][i] = 0.f; acc1[nt][i] = 0.f; }

    for (int ks = 0; ks < 128; ks += 32) {
        // ---- stage X: split fp32 -> bf16 hi|mid ----
#pragma unroll
        for (int t = 0; t < 4; ++t) {
            int i  = tid + t * 256;      // 0..1023
            int r  = i >> 3;             // 0..127
            int c4 = (i & 7) * 4;        // 0..28
            int gr = m0 + r;
            float4 v = make_float4(0.f, 0.f, 0.f, 0.f);
            if (gr < nrows) v = *(const float4*)&x[(size_t)gr * NFEAT + ks + c4];
            const float* vf = &v.x;
            __nv_bfloat16 h[4], md[4];
#pragma unroll
            for (int e = 0; e < 4; ++e) {
                h[e]  = __float2bfloat16(vf[e]);
                md[e] = __float2bfloat16(vf[e] - __bfloat162float(h[e]));
            }
            __nv_bfloat162 hp0 = make_bfloat162(h[0], h[1]);
            __nv_bfloat162 hp1 = make_bfloat162(h[2], h[3]);
            __nv_bfloat162 mp0 = make_bfloat162(md[0], md[1]);
            __nv_bfloat162 mp1 = make_bfloat162(md[2], md[3]);
            *(uint2*)&sh.s.X[r][c4]      = make_uint2(*(uint32_t*)&hp0, *(uint32_t*)&hp1);
            *(uint2*)&sh.s.X[r][32 + c4] = make_uint2(*(uint32_t*)&mp0, *(uint32_t*)&mp1);
        }
        // ---- stage W from pre-split g_wprep (clean uint4 copy) ----
#pragma unroll
        for (int t = 0; t < 4; ++t) {
            int i = tid + t * 256;       // 0..1023
            int n = i >> 3;              // 0..127
            int q = i & 7;               // q<4 -> hi chunk, q>=4 -> mid chunk
            int src_off = (q < 4) ? (ks + q * 8) : (128 + ks + (q - 4) * 8);
            uint4 val = *(const uint4*)(g_wprep + n * 256 + src_off);
            if (q < 4) *(uint4*)&sh.s.W[n][q * 8] = val;
            else       *(uint4*)&sh.s.W[n][32 + (q - 4) * 8] = val;
        }
        __syncthreads();

        // ---- compute: 2 k16-steps per chunk, 3 split passes each ----
#pragma unroll
        for (int kk = 0; kk < 32; kk += 16) {
            const int ka = kk + tg * 2;
            uint32_t ah0[4], am0[4], ah1[4], am1[4];
            ah0[0] = *(uint32_t*)&sh.s.X[rbase + g     ][ka];
            ah0[1] = *(uint32_t*)&sh.s.X[rbase + g + 8 ][ka];
            ah0[2] = *(uint32_t*)&sh.s.X[rbase + g     ][ka + 8];
            ah0[3] = *(uint32_t*)&sh.s.X[rbase + g + 8 ][ka + 8];
            am0[0] = *(uint32_t*)&sh.s.X[rbase + g     ][32 + ka];
            am0[1] = *(uint32_t*)&sh.s.X[rbase + g + 8 ][32 + ka];
            am0[2] = *(uint32_t*)&sh.s.X[rbase + g     ][32 + ka + 8];
            am0[3] = *(uint32_t*)&sh.s.X[rbase + g + 8 ][32 + ka + 8];
            ah1[0] = *(uint32_t*)&sh.s.X[rbase + g + 16][ka];
            ah1[1] = *(uint32_t*)&sh.s.X[rbase + g + 24][ka];
            ah1[2] = *(uint32_t*)&sh.s.X[rbase + g + 16][ka + 8];
            ah1[3] = *(uint32_t*)&sh.s.X[rbase + g + 24][ka + 8];
            am1[0] = *(uint32_t*)&sh.s.X[rbase + g + 16][32 + ka];
            am1[1] = *(uint32_t*)&sh.s.X[rbase + g + 24][32 + ka];
            am1[2] = *(uint32_t*)&sh.s.X[rbase + g + 16][32 + ka + 8];
            am1[3] = *(uint32_t*)&sh.s.X[rbase + g + 24][32 + ka + 8];

#pragma unroll
            for (int nt = 0; nt < 8; ++nt) {
                const int nc = cbase + nt * 8 + g;
                uint32_t bh0 = *(uint32_t*)&sh.s.W[nc][ka];
                uint32_t bh1 = *(uint32_t*)&sh.s.W[nc][ka + 8];
                uint32_t bm0 = *(uint32_t*)&sh.s.W[nc][32 + ka];
                uint32_t bm1 = *(uint32_t*)&sh.s.W[nc][32 + ka + 8];
                mma_bf16(acc0[nt], ah0, bh0, bh1);
                mma_bf16(acc0[nt], ah0, bm0, bm1);
                mma_bf16(acc0[nt], am0, bh0, bh1);
                mma_bf16(acc1[nt], ah1, bh0, bh1);
                mma_bf16(acc1[nt], ah1, bm0, bm1);
                mma_bf16(acc1[nt], am1, bh0, bh1);
            }
        }
        __syncthreads();
    }

    // ---- epilogue: accs -> SMEM (fp16) -> coalesced uint4 global stores ----
#pragma unroll
    for (int nt = 0; nt < 8; ++nt) {
        int col = cbase + nt * 8 + tg * 2;
        *(__half2*)&sh.O[rbase + g     ][col] = __floats2half2_rn(acc0[nt][0], acc0[nt][1]);
        *(__half2*)&sh.O[rbase + g + 8 ][col] = __floats2half2_rn(acc0[nt][2], acc0[nt][3]);
        *(__half2*)&sh.O[rbase + g + 16][col] = __floats2half2_rn(acc1[nt][0], acc1[nt][1]);
        *(__half2*)&sh.O[rbase + g + 24][col] = __floats2half2_rn(acc1[nt][2], acc1[nt][3]);
    }
    __syncthreads();
    // 128 rows x 16 uint4 (8 halves each) = 2048 stores  [FIX: full 128 cols]
#pragma unroll
    for (int t = 0; t < 8; ++t) {
        int i  = tid + t * 256;      // 0..2047
        int r  = i >> 4;             // 0..127
        int c8 = (i & 15) * 8;       // 0..120
        if ((m0 + r) < nrows)
            *(uint4*)&g_supp[(size_t)(m0 + r) * NHID + c8] = *(uint4*)&sh.O[r][c8];
    }
}

// ---------------------------------------------------------------------------
// Kernel 3: FUSED SpMM + bias + relu + frame-max + log_softmax.
// One warp per output row g; lane owns 4 features. fp16 support gather (256B/row).
// ---------------------------------------------------------------------------
__global__ __launch_bounds__(256)
void spmm_head(const float* __restrict__ bias, const float* __restrict__ eval,
               const int* __restrict__ ecol, float* __restrict__ out, int ng)
{
    const int g    = blockIdx.x * 8 + (threadIdx.x >> 5);
    const int lane = threadIdx.x & 31;
    if (g >= ng) return;
    const int fo = lane * 4;
    const float4 bb = *(const float4*)&bias[fo];

    float4 vm = make_float4(-INFINITY, -INFINITY, -INFINITY, -INFINITY);

    for (int f = 0; f < N_FRAMES; ++f) {
        const int node = f * ng + g;
        const int s = g_rowptr[node];
        const int e = g_rowptr[node + 1];

        float4 acc = make_float4(0.f, 0.f, 0.f, 0.f);
        int j = s;
        for (; j + 2 <= e; j += 2) {
            int   c0 = __ldcs(&ecol[j]),  c1 = __ldcs(&ecol[j + 1]);
            float v0 = __ldcs(&eval[j]),  v1 = __ldcs(&eval[j + 1]);
            uint2 q0 = *(const uint2*)(g_supp + (size_t)c0 * NHID + fo);
            uint2 q1 = *(const uint2*)(g_supp + (size_t)c1 * NHID + fo);
            float2 a0 = __half22float2(*(__half2*)&q0.x);
            float2 a1 = __half22float2(*(__half2*)&q0.y);
            float2 b0 = __half22float2(*(__half2*)&q1.x);
            float2 b1 = __half22float2(*(__half2*)&q1.y);
            acc.x = fmaf(v0, a0.x, acc.x); acc.y = fmaf(v0, a0.y, acc.y);
            acc.z = fmaf(v0, a1.x, acc.z); acc.w = fmaf(v0, a1.y, acc.w);
            acc.x = fmaf(v1, b0.x, acc.x); acc.y = fmaf(v1, b0.y, acc.y);
            acc.z = fmaf(v1, b1.x, acc.z); acc.w = fmaf(v1, b1.y, acc.w);
        }
        if (j < e) {
            int   c = __ldcs(&ecol[j]);
            float v = __ldcs(&eval[j]);
            uint2 q = *(const uint2*)(g_supp + (size_t)c * NHID + fo);
            float2 a0 = __half22float2(*(__half2*)&q.x);
            float2 a1 = __half22float2(*(__half2*)&q.y);
            acc.x = fmaf(v, a0.x, acc.x); acc.y = fmaf(v, a0.y, acc.y);
            acc.z = fmaf(v, a1.x, acc.z); acc.w = fmaf(v, a1.y, acc.w);
        }

        vm.x = fmaxf(vm.x, fmaxf(acc.x + bb.x, 0.f));
        vm.y = fmaxf(vm.y, fmaxf(acc.y + bb.y, 0.f));
        vm.z = fmaxf(vm.z, fmaxf(acc.z + bb.z, 0.f));
        vm.w = fmaxf(vm.w, fmaxf(acc.w + bb.w, 0.f));
    }

    // warp log_softmax over 128 features
    float m = fmaxf(fmaxf(vm.x, vm.y), fmaxf(vm.z, vm.w));
#pragma unroll
    for (int o = 16; o; o >>= 1) m = fmaxf(m, __shfl_xor_sync(0xffffffffu, m, o));

    float s = expf(vm.x - m) + expf(vm.y - m) + expf(vm.z - m) + expf(vm.w - m);
#pragma unroll
    for (int o = 16; o; o >>= 1) s += __shfl_xor_sync(0xffffffffu, s, o);

    float ls = m + logf(s);
    float4 r = make_float4(vm.x - ls, vm.y - ls, vm.z - ls, vm.w - ls);
    *(float4*)&out[(size_t)g * NHID + fo] = r;
}

// ---------------------------------------------------------------------------
extern "C" void kernel_launch(void* const* d_in, const int* in_sizes, int n_in,
                              void* d_out, int out_size)
{
    const float* x    = (const float*)d_in[0];
    const float* W    = (const float*)d_in[1];
    const float* b    = (const float*)d_in[2];
    const float* evl  = (const float*)d_in[3];
    const int*   erow = (const int*)  d_in[4];
    const int*   ecol = (const int*)  d_in[5];
    float* out = (float*)d_out;

    const int N  = in_sizes[0] / NFEAT;   // 140000
    const int E  = in_sizes[3];           // 2240000
    const int NG = N / N_FRAMES;          // 10000

    prep_w<<<128, 128>>>(W);
    rowptr_kernel<<<(N + 1 + 255) / 256, 256>>>(erow, N, E);
    gemm_bf16<<<(N + 127) / 128, 256>>>(x, N);
    spmm_head<<<(NG + 7) / 8, 256>>>(b, evl, ecol, out, NG);
}

// round 10
// speedup vs baseline: 3.1551x; 1.5752x over previous
#include <cuda_runtime.h>
#include <cuda_fp16.h>
#include <math.h>
#include <stdint.h>

#define N_NODES 140000
#define N_EDGES 2240000
#define NFEAT   128
#define NHID    128
#define N_FRAMES 14

// Scratch (allocation-free rule: device globals)
__device__ __half g_supp[(size_t)N_NODES * NHID];   // x@W in fp16 (35.8 MB, L2-resident)
__device__ __half g_wprep[NHID * NFEAT];            // W transposed: [n][k] fp16
__device__ int    g_rowptr[N_NODES + 1];

// ---------------------------------------------------------------------------
// fp16 m16n8k16 mma (fp32 accum)
// ---------------------------------------------------------------------------
__device__ __forceinline__ void mma_fp16(float* c, const uint32_t* a,
                                         uint32_t b0, uint32_t b1)
{
    asm volatile(
        "mma.sync.aligned.m16n8k16.row.col.f32.f16.f16.f32 "
        "{%0,%1,%2,%3}, {%4,%5,%6,%7}, {%8,%9}, {%0,%1,%2,%3};\n"
        : "+f"(c[0]), "+f"(c[1]), "+f"(c[2]), "+f"(c[3])
        : "r"(a[0]), "r"(a[1]), "r"(a[2]), "r"(a[3]), "r"(b0), "r"(b1));
}

// ---------------------------------------------------------------------------
// Kernel 0: W (fp32 [k][n]) -> g_wprep fp16 [n][k]
// ---------------------------------------------------------------------------
__global__ void prep_w(const float* __restrict__ W)
{
    const int k = blockIdx.x;     // 0..127
    const int n = threadIdx.x;    // 0..127
    g_wprep[n * NFEAT + k] = __float2half_rn(W[k * NHID + n]);
}

// ---------------------------------------------------------------------------
// Kernel 1: CSR row_ptr via binary search on sorted edge_row
// ---------------------------------------------------------------------------
__global__ void rowptr_kernel(const int* __restrict__ erow, int nnodes, int nedges)
{
    int n = blockIdx.x * blockDim.x + threadIdx.x;
    if (n > nnodes) return;
    int lo = 0, hi = nedges;
    while (lo < hi) {
        int mid = (lo + hi) >> 1;
        if (erow[mid] < n) lo = mid + 1;
        else hi = mid;
    }
    g_rowptr[n] = lo;
}

// ---------------------------------------------------------------------------
// Kernel 2: support = x @ W, single-pass fp16 m16n8k16, fp32 accum.
// 256 threads (8 warps). Block tile 128x128; warp = 32 rows x 64 cols.
// K chunked by 64. SMEM rows padded to 72 halves -> conflict-free frag LDS.
// ---------------------------------------------------------------------------
__global__ __launch_bounds__(256)
void gemm_fp16(const float* __restrict__ x, int nrows)
{
    __shared__ union {
        struct { __half X[128][72]; __half W[128][72]; } s;
        __half O[128][136];
    } sh;

    const int tid  = threadIdx.x;
    const int lane = tid & 31;
    const int w    = tid >> 5;
    const int g    = lane >> 2;     // 0..7
    const int tg   = lane & 3;      // 0..3
    const int rbase = (w & 3) * 32;
    const int cbase = (w >> 2) * 64;
    const int m0   = blockIdx.x * 128;

    float acc0[8][4], acc1[8][4];
#pragma unroll
    for (int nt = 0; nt < 8; ++nt)
#pragma unroll
        for (int i = 0; i < 4; ++i) { acc0[nt][i] = 0.f; acc1[nt][i] = 0.f; }

    for (int ks = 0; ks < 128; ks += 64) {
        // ---- stage X: 128 rows x 64 k fp32 -> fp16  (2048 float4 / 256 thr) ----
#pragma unroll
        for (int t = 0; t < 8; ++t) {
            int i  = tid + t * 256;      // 0..2047
            int r  = i >> 4;             // 0..127
            int c4 = (i & 15) * 4;       // 0..60
            int gr = m0 + r;
            float4 v = make_float4(0.f, 0.f, 0.f, 0.f);
            if (gr < nrows) v = *(const float4*)&x[(size_t)gr * NFEAT + ks + c4];
            __half2 p0 = __floats2half2_rn(v.x, v.y);
            __half2 p1 = __floats2half2_rn(v.z, v.w);
            *(uint2*)&sh.s.X[r][c4] = make_uint2(*(uint32_t*)&p0, *(uint32_t*)&p1);
        }
        // ---- stage W: fp16 [n][ks..ks+64)  (1024 uint4 / 256 thr) ----
#pragma unroll
        for (int t = 0; t < 4; ++t) {
            int i = tid + t * 256;       // 0..1023
            int n = i >> 3;              // 0..127
            int q = i & 7;               // 0..7 -> 8 halves each
            *(uint4*)&sh.s.W[n][q * 8] =
                *(const uint4*)(g_wprep + n * NFEAT + ks + q * 8);
        }
        __syncthreads();

        // ---- compute: 4 k16-steps ----
#pragma unroll
        for (int kk = 0; kk < 64; kk += 16) {
            const int ka = kk + tg * 2;
            uint32_t a0[4], a1[4];
            a0[0] = *(uint32_t*)&sh.s.X[rbase + g     ][ka];
            a0[1] = *(uint32_t*)&sh.s.X[rbase + g + 8 ][ka];
            a0[2] = *(uint32_t*)&sh.s.X[rbase + g     ][ka + 8];
            a0[3] = *(uint32_t*)&sh.s.X[rbase + g + 8 ][ka + 8];
            a1[0] = *(uint32_t*)&sh.s.X[rbase + g + 16][ka];
            a1[1] = *(uint32_t*)&sh.s.X[rbase + g + 24][ka];
            a1[2] = *(uint32_t*)&sh.s.X[rbase + g + 16][ka + 8];
            a1[3] = *(uint32_t*)&sh.s.X[rbase + g + 24][ka + 8];

#pragma unroll
            for (int nt = 0; nt < 8; ++nt) {
                const int nc = cbase + nt * 8 + g;
                uint32_t b0 = *(uint32_t*)&sh.s.W[nc][ka];
                uint32_t b1 = *(uint32_t*)&sh.s.W[nc][ka + 8];
                mma_fp16(acc0[nt], a0, b0, b1);
                mma_fp16(acc1[nt], a1, b0, b1);
            }
        }
        __syncthreads();
    }

    // ---- epilogue: accs -> SMEM fp16 -> coalesced uint4 stores ----
#pragma unroll
    for (int nt = 0; nt < 8; ++nt) {
        int col = cbase + nt * 8 + tg * 2;
        *(__half2*)&sh.O[rbase + g     ][col] = __floats2half2_rn(acc0[nt][0], acc0[nt][1]);
        *(__half2*)&sh.O[rbase + g + 8 ][col] = __floats2half2_rn(acc0[nt][2], acc0[nt][3]);
        *(__half2*)&sh.O[rbase + g + 16][col] = __floats2half2_rn(acc1[nt][0], acc1[nt][1]);
        *(__half2*)&sh.O[rbase + g + 24][col] = __floats2half2_rn(acc1[nt][2], acc1[nt][3]);
    }
    __syncthreads();
    // 128 rows x 16 uint4 (8 halves) = 2048 stores: full 128 cols
#pragma unroll
    for (int t = 0; t < 8; ++t) {
        int i  = tid + t * 256;      // 0..2047
        int r  = i >> 4;             // 0..127
        int c8 = (i & 15) * 8;       // 0..120
        if ((m0 + r) < nrows)
            *(uint4*)&g_supp[(size_t)(m0 + r) * NHID + c8] = *(uint4*)&sh.O[r][c8];
    }
}

// ---------------------------------------------------------------------------
// Kernel 3: FUSED SpMM + bias + relu + frame-max + log_softmax.
// One warp per output row g; lane owns 4 features (uint2 fp16 gather).
// Edge indices batch-loaded coalesced per 32 edges, shfl-broadcast ->
// gather addresses register-resident -> MLP 4 via manual unroll.
// ---------------------------------------------------------------------------
__global__ __launch_bounds__(256)
void spmm_head(const float* __restrict__ bias, const float* __restrict__ eval,
               const int* __restrict__ ecol, float* __restrict__ out, int ng)
{
    const int g    = blockIdx.x * 8 + (threadIdx.x >> 5);
    const int lane = threadIdx.x & 31;
    if (g >= ng) return;
    const int fo = lane * 4;
    const float4 bb = *(const float4*)&bias[fo];

    float4 vm = make_float4(-INFINITY, -INFINITY, -INFINITY, -INFINITY);

    for (int f = 0; f < N_FRAMES; ++f) {
        const int node = f * ng + g;
        const int s = g_rowptr[node];
        const int e = g_rowptr[node + 1];

        float4 acc = make_float4(0.f, 0.f, 0.f, 0.f);

        for (int base = s; base < e; base += 32) {
            const int idx = base + lane;
            int   cl = 0;
            float vl = 0.f;
            if (idx < e) {
                cl = __ldcs(&ecol[idx]);
                vl = __ldcs(&eval[idx]);
            }
            const int m = min(32, e - base);
            int k = 0;
            for (; k + 4 <= m; k += 4) {
                int c0 = __shfl_sync(0xffffffffu, cl, k);
                int c1 = __shfl_sync(0xffffffffu, cl, k + 1);
                int c2 = __shfl_sync(0xffffffffu, cl, k + 2);
                int c3 = __shfl_sync(0xffffffffu, cl, k + 3);
                float v0 = __shfl_sync(0xffffffffu, vl, k);
                float v1 = __shfl_sync(0xffffffffu, vl, k + 1);
                float v2 = __shfl_sync(0xffffffffu, vl, k + 2);
                float v3 = __shfl_sync(0xffffffffu, vl, k + 3);
                uint2 q0 = *(const uint2*)(g_supp + (size_t)c0 * NHID + fo);
                uint2 q1 = *(const uint2*)(g_supp + (size_t)c1 * NHID + fo);
                uint2 q2 = *(const uint2*)(g_supp + (size_t)c2 * NHID + fo);
                uint2 q3 = *(const uint2*)(g_supp + (size_t)c3 * NHID + fo);
                float2 a0 = __half22float2(*(__half2*)&q0.x);
                float2 a1 = __half22float2(*(__half2*)&q0.y);
                acc.x = fmaf(v0, a0.x, acc.x); acc.y = fmaf(v0, a0.y, acc.y);
                acc.z = fmaf(v0, a1.x, acc.z); acc.w = fmaf(v0, a1.y, acc.w);
                a0 = __half22float2(*(__half2*)&q1.x);
                a1 = __half22float2(*(__half2*)&q1.y);
                acc.x = fmaf(v1, a0.x, acc.x); acc.y = fmaf(v1, a0.y, acc.y);
                acc.z = fmaf(v1, a1.x, acc.z); acc.w = fmaf(v1, a1.y, acc.w);
                a0 = __half22float2(*(__half2*)&q2.x);
                a1 = __half22float2(*(__half2*)&q2.y);
                acc.x = fmaf(v2, a0.x, acc.x); acc.y = fmaf(v2, a0.y, acc.y);
                acc.z = fmaf(v2, a1.x, acc.z); acc.w = fmaf(v2, a1.y, acc.w);
                a0 = __half22float2(*(__half2*)&q3.x);
                a1 = __half22float2(*(__half2*)&q3.y);
                acc.x = fmaf(v3, a0.x, acc.x); acc.y = fmaf(v3, a0.y, acc.y);
                acc.z = fmaf(v3, a1.x, acc.z); acc.w = fmaf(v3, a1.y, acc.w);
            }
            for (; k < m; ++k) {
                int   c = __shfl_sync(0xffffffffu, cl, k);
                float v = __shfl_sync(0xffffffffu, vl, k);
                uint2 q = *(const uint2*)(g_supp + (size_t)c * NHID + fo);
                float2 a0 = __half22float2(*(__half2*)&q.x);
                float2 a1 = __half22float2(*(__half2*)&q.y);
                acc.x = fmaf(v, a0.x, acc.x); acc.y = fmaf(v, a0.y, acc.y);
                acc.z = fmaf(v, a1.x, acc.z); acc.w = fmaf(v, a1.y, acc.w);
            }
        }

        vm.x = fmaxf(vm.x, fmaxf(acc.x + bb.x, 0.f));
        vm.y = fmaxf(vm.y, fmaxf(acc.y + bb.y, 0.f));
        vm.z = fmaxf(vm.z, fmaxf(acc.z + bb.z, 0.f));
        vm.w = fmaxf(vm.w, fmaxf(acc.w + bb.w, 0.f));
    }

    // warp log_softmax over 128 features
    float m = fmaxf(fmaxf(vm.x, vm.y), fmaxf(vm.z, vm.w));
#pragma unroll
    for (int o = 16; o; o >>= 1) m = fmaxf(m, __shfl_xor_sync(0xffffffffu, m, o));

    float s = expf(vm.x - m) + expf(vm.y - m) + expf(vm.z - m) + expf(vm.w - m);
#pragma unroll
    for (int o = 16; o; o >>= 1) s += __shfl_xor_sync(0xffffffffu, s, o);

    float ls = m + logf(s);
    float4 r = make_float4(vm.x - ls, vm.y - ls, vm.z - ls, vm.w - ls);
    *(float4*)&out[(size_t)g * NHID + fo] = r;
}

// ---------------------------------------------------------------------------
extern "C" void kernel_launch(void* const* d_in, const int* in_sizes, int n_in,
                              void* d_out, int out_size)
{
    const float* x    = (const float*)d_in[0];
    const float* W    = (const float*)d_in[1];
    const float* b    = (const float*)d_in[2];
    const float* evl  = (const float*)d_in[3];
    const int*   erow = (const int*)  d_in[4];
    const int*   ecol = (const int*)  d_in[5];
    float* out = (float*)d_out;

    const int N  = in_sizes[0] / NFEAT;   // 140000
    const int E  = in_sizes[3];           // 2240000
    const int NG = N / N_FRAMES;          // 10000

    prep_w<<<128, 128>>>(W);
    rowptr_kernel<<<(N + 1 + 255) / 256, 256>>>(erow, N, E);
    gemm_fp16<<<(N + 127) / 128, 256>>>(x, N);
    spmm_head<<<(NG + 7) / 8, 256>>>(b, evl, ecol, out, NG);
}